// round 1
// baseline (speedup 1.0000x reference)
#include <cuda_runtime.h>
#include <cstdint>

// ---------------- problem constants ----------------
#define T     2048
#define DIN   512
#define DOUT  512
#define KF    24
#define NC    48          // 2 * KF  (plus / minus channels)
#define KU    3
#define BT    128         // time block
#define NBLK  16          // T / BT
#define SPLIT 5           // deterministic split-K for conv GEMM

// ---------------- device scratch (no allocations allowed) ----------------
__device__ float g_Z[(size_t)NC * T * DOUT];        // 48*2048*512 fp32 = 201 MB
__device__ float g_part[(size_t)SPLIT * T * DOUT];  // split-K partials
__device__ float g_phiT[NC * T];                    // phi transposed + (-1)^s for minus
__device__ float g_MT[KU * DIN * DOUT];             // M transposed: [tau][d][o]

// ---------------- helpers ----------------
__device__ __forceinline__ float f2tf32(float v) {
    uint32_t u;
    asm("cvt.rna.tf32.f32 %0, %1;" : "=r"(u) : "f"(v));
    return __uint_as_float(u);
}

__device__ __forceinline__ void mma_tf32(float* c, const uint32_t* a, const uint32_t* b) {
    asm("mma.sync.aligned.m16n8k8.row.col.f32.tf32.tf32.f32 "
        "{%0,%1,%2,%3}, {%4,%5,%6,%7}, {%8,%9}, {%0,%1,%2,%3};"
        : "+f"(c[0]), "+f"(c[1]), "+f"(c[2]), "+f"(c[3])
        : "r"(a[0]), "r"(a[1]), "r"(a[2]), "r"(a[3]),
          "r"(b[0]), "r"(b[1]));
}

// ---------------- prep: phiT and MT ----------------
__global__ void prep_kernel(const float* __restrict__ phi, const float* __restrict__ M) {
    int idx = blockIdx.x * blockDim.x + threadIdx.x;
    if (idx < NC * T) {
        int c = idx / T, s = idx - c * T;
        int k = (c < KF) ? c : c - KF;
        float v = phi[s * KF + k];
        if (c >= KF && (s & 1)) v = -v;     // phi_minus[s] = (-1)^s phi[s]
        g_phiT[idx] = v;
    }
    int r = idx - NC * T;
    if (r >= 0 && r < KU * DIN * DOUT) {
        int tau = r / (DIN * DOUT);
        int rem = r - tau * (DIN * DOUT);
        int d = rem / DOUT, o = rem - d * DOUT;
        g_MT[r] = M[((size_t)o * DIN + d) * KU + tau];
    }
}

// ---------------- GEMM1: Z[c][t][o] = sum_d x[t,d] * M_c[k][d][o] ----------------
__global__ void __launch_bounds__(256) gemm1_kernel(
    const float* __restrict__ x, const float* __restrict__ Mp, const float* __restrict__ Mm)
{
    __shared__ float As[32][BT + 4];   // [k][m]
    __shared__ float Bs[32][BT + 4];   // [k][n]

    const int tTile = blockIdx.x, oTile = blockIdx.y, c = blockIdx.z;
    const float* W = (c < KF) ? (Mp + (size_t)c * DIN * DOUT)
                              : (Mm + (size_t)(c - KF) * DIN * DOUT);
    const int t0 = tTile * BT, n0 = oTile * BT;
    const int tid = threadIdx.x;
    const int warp = tid >> 5, lane = tid & 31;
    const int wm = warp >> 2, wn = warp & 3;          // 2x4 warps, warp tile 64x32
    const int mbase = wm * 64, nbase = wn * 32;
    const int tg = lane >> 2, tig = lane & 3;

    float acc[4][4][4];
    #pragma unroll
    for (int a0 = 0; a0 < 4; ++a0)
        #pragma unroll
        for (int b0 = 0; b0 < 4; ++b0)
            #pragma unroll
            for (int e = 0; e < 4; ++e) acc[a0][b0][e] = 0.f;

    for (int kt = 0; kt < DIN; kt += 32) {
        #pragma unroll
        for (int it = 0; it < 4; ++it) {            // A: x tile 128x32 -> transposed smem
            int fl = tid + it * 256;
            int r = fl >> 3;
            int c4 = (fl & 7) << 2;
            float4 v = *(const float4*)(x + (size_t)(t0 + r) * DIN + kt + c4);
            As[c4 + 0][r] = f2tf32(v.x); As[c4 + 1][r] = f2tf32(v.y);
            As[c4 + 2][r] = f2tf32(v.z); As[c4 + 3][r] = f2tf32(v.w);
        }
        #pragma unroll
        for (int it = 0; it < 4; ++it) {            // B: W tile 32x128
            int fl = tid + it * 256;
            int rr = fl >> 5;
            int o4 = (fl & 31) << 2;
            float4 v = *(const float4*)(W + (size_t)(kt + rr) * DOUT + n0 + o4);
            float4 w = make_float4(f2tf32(v.x), f2tf32(v.y), f2tf32(v.z), f2tf32(v.w));
            *(float4*)&Bs[rr][o4] = w;
        }
        __syncthreads();
        #pragma unroll
        for (int ks = 0; ks < 32; ks += 8) {
            uint32_t af[4][4], bf[4][2];
            #pragma unroll
            for (int mf = 0; mf < 4; ++mf) {
                int r0 = mbase + mf * 16;
                af[mf][0] = __float_as_uint(As[ks + tig][r0 + tg]);
                af[mf][1] = __float_as_uint(As[ks + tig][r0 + tg + 8]);
                af[mf][2] = __float_as_uint(As[ks + tig + 4][r0 + tg]);
                af[mf][3] = __float_as_uint(As[ks + tig + 4][r0 + tg + 8]);
            }
            #pragma unroll
            for (int nf = 0; nf < 4; ++nf) {
                int c0 = nbase + nf * 8;
                bf[nf][0] = __float_as_uint(Bs[ks + tig][c0 + tg]);
                bf[nf][1] = __float_as_uint(Bs[ks + tig + 4][c0 + tg]);
            }
            #pragma unroll
            for (int mf = 0; mf < 4; ++mf)
                #pragma unroll
                for (int nf = 0; nf < 4; ++nf)
                    mma_tf32(acc[mf][nf], af[mf], bf[nf]);
        }
        __syncthreads();
    }

    float* Zc = g_Z + (size_t)c * T * DOUT;
    #pragma unroll
    for (int mf = 0; mf < 4; ++mf) {
        int r0 = t0 + mbase + mf * 16 + tg;
        #pragma unroll
        for (int nf = 0; nf < 4; ++nf) {
            int c0 = n0 + nbase + nf * 8 + tig * 2;
            Zc[(size_t)r0 * DOUT + c0]           = acc[mf][nf][0];
            Zc[(size_t)r0 * DOUT + c0 + 1]       = acc[mf][nf][1];
            Zc[(size_t)(r0 + 8) * DOUT + c0]     = acc[mf][nf][2];
            Zc[(size_t)(r0 + 8) * DOUT + c0 + 1] = acc[mf][nf][3];
        }
    }
}

// -------- GEMM2: out[t,o] = sum_c (phi_c (*) Z_c)[t,o] + AR, blocked Toeplitz --------
__global__ void __launch_bounds__(256) gemm2_kernel(const float* __restrict__ x)
{
    __shared__ float Bs[32][BT + 4];
    __shared__ float Asm[32][BT + 4];   // AR A tile (transposed x)
    __shared__ float seg[160];          // phi segment for Toeplitz tile

    const int bx = blockIdx.x;
    const int i = bx >> 2, ot = bx & 3, sp = blockIdx.y;
    const int t0 = i * BT, n0 = ot * BT;
    const int tid = threadIdx.x;
    const int warp = tid >> 5, lane = tid & 31;
    const int wm = warp >> 2, wn = warp & 3;
    const int mbase = wm * 64, nbase = wn * 32;
    const int tg = lane >> 2, tig = lane & 3;

    float acc[4][4][4];
    #pragma unroll
    for (int a0 = 0; a0 < 4; ++a0)
        #pragma unroll
        for (int b0 = 0; b0 < 4; ++b0)
            #pragma unroll
            for (int e = 0; e < 4; ++e) acc[a0][b0][e] = 0.f;

    const int per = (i + 1) * 4;        // K=32 chunks per channel
    const int nconv = NC * per;
    const int ntot = nconv + KU * (DIN / 32);

    for (int q = sp; q < ntot; q += SPLIT) {
        const bool isconv = (q < nconv);
        if (isconv) {
            int cch = q / per;
            int rem = q - cch * per;
            int j = rem >> 2;
            int ks0 = (rem & 3) << 5;
            // B tile: Z_c rows [j*128+ks0 .. +31], cols [n0..n0+127]
            const float* Zc = g_Z + ((size_t)cch * T + j * BT + ks0) * DOUT + n0;
            #pragma unroll
            for (int it = 0; it < 4; ++it) {
                int fl = tid + it * 256;
                int rr = fl >> 5, o4 = (fl & 31) << 2;
                float4 v = *(const float4*)(Zc + (size_t)rr * DOUT + o4);
                float4 w = make_float4(f2tf32(v.x), f2tf32(v.y), f2tf32(v.z), f2tf32(v.w));
                *(float4*)&Bs[rr][o4] = w;
            }
            // phi segment: P[a][kk] = phiT[c][(i-j)*128 + a - (ks0+kk)] = seg[a-kk+31]
            int sbase = (i - j) * BT - ks0 - 31;
            for (int u = tid; u < 160; u += 256) {
                int s = sbase + u;
                seg[u] = (s >= 0 && s < T) ? f2tf32(g_phiT[cch * T + s]) : 0.f;
            }
        } else {
            int r = q - nconv;
            int tau = r >> 4;
            int ks0 = (r & 15) << 5;
            const float* Wt = g_MT + ((size_t)tau * DIN + ks0) * DOUT + n0;
            #pragma unroll
            for (int it = 0; it < 4; ++it) {
                int fl = tid + it * 256;
                int rr = fl >> 5, o4 = (fl & 31) << 2;
                float4 v = *(const float4*)(Wt + (size_t)rr * DOUT + o4);
                float4 w = make_float4(f2tf32(v.x), f2tf32(v.y), f2tf32(v.z), f2tf32(v.w));
                *(float4*)&Bs[rr][o4] = w;
            }
            #pragma unroll
            for (int it = 0; it < 4; ++it) {   // A tile: x rows shifted by tau, transposed
                int fl = tid + it * 256;
                int a = fl >> 3;
                int c4 = (fl & 7) << 2;
                int row = t0 + a - tau;
                float4 v = (row >= 0)
                    ? *(const float4*)(x + (size_t)row * DIN + ks0 + c4)
                    : make_float4(0.f, 0.f, 0.f, 0.f);
                Asm[c4 + 0][a] = f2tf32(v.x); Asm[c4 + 1][a] = f2tf32(v.y);
                Asm[c4 + 2][a] = f2tf32(v.z); Asm[c4 + 3][a] = f2tf32(v.w);
            }
        }
        __syncthreads();

        if (isconv) {
            #pragma unroll
            for (int ks = 0; ks < 32; ks += 8) {
                uint32_t af[4][4], bf[4][2];
                #pragma unroll
                for (int mf = 0; mf < 4; ++mf) {
                    int u0 = mbase + mf * 16 + tg - ks - tig + 31;
                    af[mf][0] = __float_as_uint(seg[u0]);
                    af[mf][1] = __float_as_uint(seg[u0 + 8]);
                    af[mf][2] = __float_as_uint(seg[u0 - 4]);
                    af[mf][3] = __float_as_uint(seg[u0 + 4]);
                }
                #pragma unroll
                for (int nf = 0; nf < 4; ++nf) {
                    int c0 = nbase + nf * 8;
                    bf[nf][0] = __float_as_uint(Bs[ks + tig][c0 + tg]);
                    bf[nf][1] = __float_as_uint(Bs[ks + tig + 4][c0 + tg]);
                }
                #pragma unroll
                for (int mf = 0; mf < 4; ++mf)
                    #pragma unroll
                    for (int nf = 0; nf < 4; ++nf)
                        mma_tf32(acc[mf][nf], af[mf], bf[nf]);
            }
        } else {
            #pragma unroll
            for (int ks = 0; ks < 32; ks += 8) {
                uint32_t af[4][4], bf[4][2];
                #pragma unroll
                for (int mf = 0; mf < 4; ++mf) {
                    int r0 = mbase + mf * 16;
                    af[mf][0] = __float_as_uint(Asm[ks + tig][r0 + tg]);
                    af[mf][1] = __float_as_uint(Asm[ks + tig][r0 + tg + 8]);
                    af[mf][2] = __float_as_uint(Asm[ks + tig + 4][r0 + tg]);
                    af[mf][3] = __float_as_uint(Asm[ks + tig + 4][r0 + tg + 8]);
                }
                #pragma unroll
                for (int nf = 0; nf < 4; ++nf) {
                    int c0 = nbase + nf * 8;
                    bf[nf][0] = __float_as_uint(Bs[ks + tig][c0 + tg]);
                    bf[nf][1] = __float_as_uint(Bs[ks + tig + 4][c0 + tg]);
                }
                #pragma unroll
                for (int mf = 0; mf < 4; ++mf)
                    #pragma unroll
                    for (int nf = 0; nf < 4; ++nf)
                        mma_tf32(acc[mf][nf], af[mf], bf[nf]);
            }
        }
        __syncthreads();
    }

    float* P = g_part + (size_t)sp * T * DOUT;
    #pragma unroll
    for (int mf = 0; mf < 4; ++mf) {
        int r0 = t0 + mbase + mf * 16 + tg;
        #pragma unroll
        for (int nf = 0; nf < 4; ++nf) {
            int c0 = n0 + nbase + nf * 8 + tig * 2;
            P[(size_t)r0 * DOUT + c0]           = acc[mf][nf][0];
            P[(size_t)r0 * DOUT + c0 + 1]       = acc[mf][nf][1];
            P[(size_t)(r0 + 8) * DOUT + c0]     = acc[mf][nf][2];
            P[(size_t)(r0 + 8) * DOUT + c0 + 1] = acc[mf][nf][3];
        }
    }
}

// ---------------- reduce split-K partials ----------------
__global__ void reduce_kernel(float* __restrict__ out) {
    size_t idx = (size_t)(blockIdx.x * blockDim.x + threadIdx.x) * 4;
    float4 s = make_float4(0.f, 0.f, 0.f, 0.f);
    #pragma unroll
    for (int p = 0; p < SPLIT; ++p) {
        float4 v = *(const float4*)(g_part + (size_t)p * T * DOUT + idx);
        s.x += v.x; s.y += v.y; s.z += v.z; s.w += v.w;
    }
    *(float4*)(out + idx) = s;
}

// ---------------- entry ----------------
extern "C" void kernel_launch(void* const* d_in, const int* in_sizes, int n_in,
                              void* d_out, int out_size) {
    const float* x   = (const float*)d_in[0];
    const float* phi = (const float*)d_in[1];
    const float* M   = (const float*)d_in[2];
    const float* Mp  = (const float*)d_in[3];
    const float* Mm  = (const float*)d_in[4];
    float* out = (float*)d_out;

    prep_kernel<<<(NC * T + KU * DIN * DOUT + 255) / 256, 256>>>(phi, M);
    gemm1_kernel<<<dim3(NBLK, 4, NC), 256>>>(x, Mp, Mm);
    gemm2_kernel<<<dim3(NBLK * 4, SPLIT), 256>>>(x);
    reduce_kernel<<<(T * DOUT / 4 + 255) / 256, 256>>>(out);
}